// round 1
// baseline (speedup 1.0000x reference)
#include <cuda_runtime.h>
#include <math_constants.h>

// Problem constants
// x: [4,16,8192] f32 ; weights1: [16,16,64] f32 ; out: [4,16,4097] f32
#define RWS   64      // B*Cin == B*Cout == 64 rows
#define NN    8192
#define MM    64
#define N2    4097
#define NPART 128     // split-K partial blocks for stage-1 GEMM

// -------- device scratch (no allocations allowed) --------
__device__ float g_P[NPART * RWS * MM];   // stage-1 partials [p][r*64+k]  (2 MB)
__device__ float g_Y[RWS * MM];           // reduced Y[r][k]
__device__ float g_hq[MM * 256];          // hq transposed: [m][u], u = i*16+o
__device__ float g_cs64[MM * MM];         // cas64[j][m]
__device__ float g_hz[RWS * MM];          // hz[bo][m]
__device__ float g_zT[MM * RWS];          // z transposed: [m][r]

// ============================================================
// K1: blocks [0,128): partial Y = X @ cas8192[:, :64]   (split over n)
//     blocks [128,144): hq = W @ cas64  (transposed store)
//     block 144: cas64 table
// ============================================================
__global__ void k_stage1(const float* __restrict__ x, const float* __restrict__ w)
{
    __shared__ float Xs[64][68];   // [n_local][r], padded
    __shared__ float Cs[64][68];   // [n_local][k] / [j][m], padded
    __shared__ float ws[16][64];

    const int blk = blockIdx.x;
    const int tid = threadIdx.x;

    if (blk < NPART) {
        // ---- partial GEMM: P[r][k] = sum_{nl} X[r][n0+nl] * cas((n0+nl)*k / 8192)
        const int n0 = blk * 64;
        // load X chunk, transposed into smem
        for (int idx = tid; idx < 64 * 16; idx += 256) {
            int row = idx >> 4;
            int c4  = (idx & 15) * 4;
            float4 v = *reinterpret_cast<const float4*>(x + row * NN + n0 + c4);
            Xs[c4 + 0][row] = v.x;
            Xs[c4 + 1][row] = v.y;
            Xs[c4 + 2][row] = v.z;
            Xs[c4 + 3][row] = v.w;
        }
        // cas values for this n-chunk (exact period reduction: N power of two)
        const float W0 = 2.0f * CUDART_PI_F / 8192.0f;
        for (int idx = tid; idx < 4096; idx += 256) {
            int nl = idx >> 6, k = idx & 63;
            unsigned t = ((unsigned)(n0 + nl) * (unsigned)k) & 8191u;
            float s, c;
            __sincosf((float)t * W0, &s, &c);
            Cs[nl][k] = c + s;
        }
        __syncthreads();

        const int kq = tid & 15, rq = tid >> 4;
        const int r0 = rq * 4, k0 = kq * 4;
        float acc[4][4] = {};
        #pragma unroll
        for (int nl = 0; nl < 64; nl++) {
            float4 xv = *reinterpret_cast<const float4*>(&Xs[nl][r0]);
            float4 cv = *reinterpret_cast<const float4*>(&Cs[nl][k0]);
            float xr[4] = {xv.x, xv.y, xv.z, xv.w};
            float ck[4] = {cv.x, cv.y, cv.z, cv.w};
            #pragma unroll
            for (int a = 0; a < 4; a++)
                #pragma unroll
                for (int b = 0; b < 4; b++)
                    acc[a][b] = fmaf(xr[a], ck[b], acc[a][b]);
        }
        float* P = g_P + blk * (RWS * MM);
        #pragma unroll
        for (int a = 0; a < 4; a++) {
            float4 v = make_float4(acc[a][0], acc[a][1], acc[a][2], acc[a][3]);
            *reinterpret_cast<float4*>(P + (r0 + a) * 64 + k0) = v;
        }
    } else if (blk < 144) {
        // ---- hq block: rows u0..u0+15 of W (u = i*16+o), hq[u][m] = sum_j w[u][j]*cas64[j][m]
        const int u0 = (blk - 128) * 16;
        for (int idx = tid; idx < 1024; idx += 256)
            ws[idx >> 6][idx & 63] = w[u0 * 64 + idx];
        const float W1 = 2.0f * CUDART_PI_F / 64.0f;
        for (int idx = tid; idx < 4096; idx += 256) {
            int j = idx >> 6, m = idx & 63;
            unsigned t = ((unsigned)j * (unsigned)m) & 63u;
            float s, c;
            __sincosf((float)t * W1, &s, &c);
            Cs[j][m] = c + s;
        }
        __syncthreads();

        const int ul = tid >> 4, mq = tid & 15, m0 = mq * 4;
        float acc[4] = {};
        #pragma unroll
        for (int j = 0; j < 64; j++) {
            float wv = ws[ul][j];
            float4 cv = *reinterpret_cast<const float4*>(&Cs[j][m0]);
            acc[0] = fmaf(wv, cv.x, acc[0]);
            acc[1] = fmaf(wv, cv.y, acc[1]);
            acc[2] = fmaf(wv, cv.z, acc[2]);
            acc[3] = fmaf(wv, cv.w, acc[3]);
        }
        #pragma unroll
        for (int e = 0; e < 4; e++)
            g_hq[(m0 + e) * 256 + u0 + ul] = acc[e];
    } else {
        // ---- cas64 table to gmem
        const float W1 = 2.0f * CUDART_PI_F / 64.0f;
        for (int idx = tid; idx < 4096; idx += 256) {
            int j = idx >> 6, m = idx & 63;
            unsigned t = ((unsigned)j * (unsigned)m) & 63u;
            float s, c;
            __sincosf((float)t * W1, &s, &c);
            g_cs64[idx] = c + s;
        }
    }
}

// ============================================================
// K2: reduce partials -> Y
// ============================================================
__global__ void k_reduce()
{
    const int j = blockIdx.x * 128 + threadIdx.x;  // 0..4095
    float a0 = 0.f, a1 = 0.f, a2 = 0.f, a3 = 0.f;
    #pragma unroll 4
    for (int p = 0; p < NPART; p += 4) {
        a0 += g_P[(p + 0) * 4096 + j];
        a1 += g_P[(p + 1) * 4096 + j];
        a2 += g_P[(p + 2) * 4096 + j];
        a3 += g_P[(p + 3) * 4096 + j];
    }
    g_Y[j] = (a0 + a1) + (a2 + a3);
}

// ============================================================
// K3: per-m block: hp[:,m], hp[:,mr] -> u,v -> hz[:,m]
//   hz[b,o,m] = 0.5*sum_i( (hp+rp)[b,i,m]*hq[i,o,m] + (hp-rp)[b,i,m]*hq[i,o,mr] )
// ============================================================
__global__ void k_hz()
{
    __shared__ float Ys[64][65];
    __shared__ float cm[64], cmr[64];
    __shared__ float us[64], vs[64];
    __shared__ float hqm[256], hqmr[256];

    const int m  = blockIdx.x;
    const int mr = (64 - m) & 63;
    const int tid = threadIdx.x;   // 64 threads

    for (int idx = tid; idx < 4096; idx += 64)
        Ys[idx >> 6][idx & 63] = g_Y[idx];
    cm[tid]  = g_cs64[tid * 64 + m];
    cmr[tid] = g_cs64[tid * 64 + mr];
    for (int idx = tid; idx < 256; idx += 64) {
        hqm[idx]  = g_hq[m  * 256 + idx];
        hqmr[idx] = g_hq[mr * 256 + idx];
    }
    __syncthreads();

    // hp for this column and its reverse
    float am = 0.f, amr = 0.f;
    #pragma unroll
    for (int j = 0; j < 64; j++) {
        float yv = Ys[tid][j];
        am  = fmaf(yv, cm[j],  am);
        amr = fmaf(yv, cmr[j], amr);
    }
    us[tid] = am + amr;
    vs[tid] = am - amr;
    __syncthreads();

    const int b = tid >> 4, o = tid & 15;
    float acc = 0.f;
    #pragma unroll
    for (int i = 0; i < 16; i++) {
        acc = fmaf(us[b * 16 + i], hqm [i * 16 + o], acc);
        acc = fmaf(vs[b * 16 + i], hqmr[i * 16 + o], acc);
    }
    g_hz[tid * 64 + m] = 0.5f * acc;
}

// ============================================================
// K4: z = (hz @ cas64) / 4096, stored transposed [m'][r]
// ============================================================
__global__ void k_z()
{
    __shared__ float hzs[4][64];
    __shared__ float cs[64][64];

    const int blk = blockIdx.x;     // 16 blocks, 4 rows each
    const int tid = threadIdx.x;    // 256
    const int r0 = blk * 4;

    hzs[tid >> 6][tid & 63] = g_hz[r0 * 64 + tid];
    for (int idx = tid; idx < 4096; idx += 256)
        cs[idx >> 6][idx & 63] = g_cs64[idx];
    __syncthreads();

    const int rl = tid >> 6, mp = tid & 63;
    float acc = 0.f;
    #pragma unroll
    for (int m = 0; m < 64; m++)
        acc = fmaf(hzs[rl][m], cs[m][mp], acc);
    g_zT[mp * 64 + r0 + rl] = acc * (1.0f / 4096.0f);
}

// ============================================================
// K5: out[r][k] = (sum_m z[r][m] * cas(2*pi*m*k/4097)) / 262208
// ============================================================
__global__ void k_out(float* __restrict__ out)
{
    __shared__ float zs[64][68];   // [m][r] padded
    __shared__ float Cs[64][36];   // [m][kt] padded (float2-aligned)

    const int blk = blockIdx.x;          // 129 blocks, 32 k each
    const int tid = threadIdx.x;         // 256
    const int kbase = blk * 32;

    for (int idx = tid; idx < 4096; idx += 256)
        zs[idx >> 6][idx & 63] = g_zT[idx];

    const float W2 = 2.0f * CUDART_PI_F / 4097.0f;
    for (int idx = tid; idx < 2048; idx += 256) {
        int mm = idx >> 5, kt = idx & 31;
        int k = kbase + kt;
        float val = 0.f;
        if (k < N2) {
            int t = (mm * k) % 4097;
            float s, c;
            __sincosf((float)t * W2, &s, &c);
            val = c + s;
        }
        Cs[mm][kt] = val;
    }
    __syncthreads();

    const int ktq = tid & 15, rq = tid >> 4;
    const int r0 = rq * 4, k0 = ktq * 2;
    float acc[4][2] = {};
    #pragma unroll
    for (int mm = 0; mm < 64; mm++) {
        float4 zv = *reinterpret_cast<const float4*>(&zs[mm][r0]);
        float2 cv = *reinterpret_cast<const float2*>(&Cs[mm][k0]);
        acc[0][0] = fmaf(zv.x, cv.x, acc[0][0]);
        acc[0][1] = fmaf(zv.x, cv.y, acc[0][1]);
        acc[1][0] = fmaf(zv.y, cv.x, acc[1][0]);
        acc[1][1] = fmaf(zv.y, cv.y, acc[1][1]);
        acc[2][0] = fmaf(zv.z, cv.x, acc[2][0]);
        acc[2][1] = fmaf(zv.z, cv.y, acc[2][1]);
        acc[3][0] = fmaf(zv.w, cv.x, acc[3][0]);
        acc[3][1] = fmaf(zv.w, cv.y, acc[3][1]);
    }
    const float SCL = 1.0f / 262208.0f;
    #pragma unroll
    for (int ri = 0; ri < 4; ri++) {
        #pragma unroll
        for (int ki = 0; ki < 2; ki++) {
            int k = kbase + k0 + ki;
            if (k < N2)
                out[(r0 + ri) * N2 + k] = acc[ri][ki] * SCL;
        }
    }
}

// ============================================================
extern "C" void kernel_launch(void* const* d_in, const int* in_sizes, int n_in,
                              void* d_out, int out_size)
{
    const float* x = (const float*)d_in[0];   // [4,16,8192]
    const float* w = (const float*)d_in[1];   // [16,16,64]
    float* out = (float*)d_out;               // [4,16,4097]

    k_stage1<<<145, 256>>>(x, w);
    k_reduce<<<32, 128>>>();
    k_hz<<<64, 64>>>();
    k_z<<<16, 256>>>();
    k_out<<<129, 256>>>(out);
}

// round 2
// speedup vs baseline: 1.2506x; 1.2506x over previous
#include <cuda_runtime.h>
#include <math_constants.h>

// x: [4,16,8192] f32 ; weights1: [16,16,64] f32 ; out: [4,16,4097] f32
#define RWS   64      // B*Cin == B*Cout == 64 rows
#define NN    8192
#define MM    64
#define N2    4097
#define NPART 128     // split-K partial blocks for stage-1 GEMM

// -------- device scratch --------
__device__ float g_P[NPART * RWS * MM];   // stage-1 partials [p][r*64+k]  (2 MB)
__device__ float g_hq[MM * 256];          // hq transposed: [m][u], u = i*16+o
__device__ float g_zT[MM * RWS];          // z transposed: [m'][r]

// ============================================================
// K1: blocks [0,128): partial Y = X @ cas8192[:, :64]  (split over n)
//     blocks [128,144): hq = W @ cas64  (transposed store)
// ============================================================
__global__ void k_stage1(const float* __restrict__ x, const float* __restrict__ w)
{
    __shared__ float Xs[64][68];   // [n_local][r], padded
    __shared__ float Cs[64][68];   // [n_local][k] / [j][m], padded
    __shared__ float ws[16][64];

    const int blk = blockIdx.x;
    const int tid = threadIdx.x;

    if (blk < NPART) {
        const int n0 = blk * 64;
        for (int idx = tid; idx < 64 * 16; idx += 256) {
            int row = idx >> 4;
            int c4  = (idx & 15) * 4;
            float4 v = *reinterpret_cast<const float4*>(x + row * NN + n0 + c4);
            Xs[c4 + 0][row] = v.x;
            Xs[c4 + 1][row] = v.y;
            Xs[c4 + 2][row] = v.z;
            Xs[c4 + 3][row] = v.w;
        }
        const float W0 = 2.0f * CUDART_PI_F / 8192.0f;
        for (int idx = tid; idx < 4096; idx += 256) {
            int nl = idx >> 6, k = idx & 63;
            unsigned t = ((unsigned)(n0 + nl) * (unsigned)k) & 8191u;
            float s, c;
            __sincosf((float)t * W0, &s, &c);
            Cs[nl][k] = c + s;
        }
        __syncthreads();

        const int kq = tid & 15, rq = tid >> 4;
        const int r0 = rq * 4, k0 = kq * 4;
        float acc[4][4] = {};
        #pragma unroll
        for (int nl = 0; nl < 64; nl++) {
            float4 xv = *reinterpret_cast<const float4*>(&Xs[nl][r0]);
            float4 cv = *reinterpret_cast<const float4*>(&Cs[nl][k0]);
            float xr[4] = {xv.x, xv.y, xv.z, xv.w};
            float ck[4] = {cv.x, cv.y, cv.z, cv.w};
            #pragma unroll
            for (int a = 0; a < 4; a++)
                #pragma unroll
                for (int b = 0; b < 4; b++)
                    acc[a][b] = fmaf(xr[a], ck[b], acc[a][b]);
        }
        float* P = g_P + blk * (RWS * MM);
        #pragma unroll
        for (int a = 0; a < 4; a++) {
            float4 v = make_float4(acc[a][0], acc[a][1], acc[a][2], acc[a][3]);
            *reinterpret_cast<float4*>(P + (r0 + a) * 64 + k0) = v;
        }
    } else {
        // hq block: rows u0..u0+15 (u = i*16+o): hq[u][m'] = sum_j w[u][j]*cas64[j][m']
        const int u0 = (blk - 128) * 16;
        for (int idx = tid; idx < 1024; idx += 256)
            ws[idx >> 6][idx & 63] = w[u0 * 64 + idx];
        const float W1 = 2.0f * CUDART_PI_F / 64.0f;
        for (int idx = tid; idx < 4096; idx += 256) {
            int j = idx >> 6, m = idx & 63;
            unsigned t = ((unsigned)j * (unsigned)m) & 63u;
            float s, c;
            __sincosf((float)t * W1, &s, &c);
            Cs[j][m] = c + s;
        }
        __syncthreads();

        const int ul = tid >> 4, mq = tid & 15, m0 = mq * 4;
        float acc[4] = {};
        #pragma unroll
        for (int j = 0; j < 64; j++) {
            float wv = ws[ul][j];
            float4 cv = *reinterpret_cast<const float4*>(&Cs[j][m0]);
            acc[0] = fmaf(wv, cv.x, acc[0]);
            acc[1] = fmaf(wv, cv.y, acc[1]);
            acc[2] = fmaf(wv, cv.z, acc[2]);
            acc[3] = fmaf(wv, cv.w, acc[3]);
        }
        #pragma unroll
        for (int e = 0; e < 4; e++)
            g_hq[(m0 + e) * 256 + u0 + ul] = acc[e];
    }
}

// ============================================================
// K2: fused reduce + hp + (u,v) + hz + z.  One block per batch b (4 blocks).
//   Block b owns Y rows r in [16b, 16b+16) == (b, i) for i in [0,16).
// ============================================================
__global__ void k_mid()
{
    __shared__ float Ys [16][68];
    __shared__ float cs [64][68];
    __shared__ float hps[16][68];
    __shared__ float us [16][68];
    __shared__ float vs [16][68];
    __shared__ float hzs[16][68];

    const int b   = blockIdx.x;
    const int tid = threadIdx.x;   // 256

    // ---- phase 0: cas64 table ----
    const float W1 = 2.0f * CUDART_PI_F / 64.0f;
    for (int idx = tid; idx < 4096; idx += 256) {
        int j = idx >> 6, m = idx & 63;
        unsigned t = ((unsigned)j * (unsigned)m) & 63u;
        float s, c;
        __sincosf((float)t * W1, &s, &c);
        cs[j][m] = c + s;
    }

    // ---- phase 1: split-K reduce for this block's 16 Y rows ----
    {
        const float* P = g_P + b * 1024 + tid * 4;
        float4 a0 = {0,0,0,0}, a1 = {0,0,0,0}, a2 = {0,0,0,0}, a3 = {0,0,0,0};
        #pragma unroll 4
        for (int p = 0; p < NPART; p += 4) {
            float4 v0 = *reinterpret_cast<const float4*>(P + (p + 0) * 4096);
            float4 v1 = *reinterpret_cast<const float4*>(P + (p + 1) * 4096);
            float4 v2 = *reinterpret_cast<const float4*>(P + (p + 2) * 4096);
            float4 v3 = *reinterpret_cast<const float4*>(P + (p + 3) * 4096);
            a0.x += v0.x; a0.y += v0.y; a0.z += v0.z; a0.w += v0.w;
            a1.x += v1.x; a1.y += v1.y; a1.z += v1.z; a1.w += v1.w;
            a2.x += v2.x; a2.y += v2.y; a2.z += v2.z; a2.w += v2.w;
            a3.x += v3.x; a3.y += v3.y; a3.z += v3.z; a3.w += v3.w;
        }
        float4 a;
        a.x = (a0.x + a1.x) + (a2.x + a3.x);
        a.y = (a0.y + a1.y) + (a2.y + a3.y);
        a.z = (a0.z + a1.z) + (a2.z + a3.z);
        a.w = (a0.w + a1.w) + (a2.w + a3.w);
        int il = tid >> 4, k0 = (tid & 15) * 4;
        *reinterpret_cast<float4*>(&Ys[il][k0]) = a;
    }
    __syncthreads();

    // ---- phase 2: hp[il][m] = sum_k Ys[il][k] * cs[k][m] ----
    #pragma unroll
    for (int q = 0; q < 4; q++) {
        int idx = tid + q * 256;
        int il = idx >> 6, m = idx & 63;
        float acc = 0.f;
        #pragma unroll
        for (int k = 0; k < 64; k++)
            acc = fmaf(Ys[il][k], cs[k][m], acc);
        hps[il][m] = acc;
    }
    __syncthreads();

    // ---- phase 3: u,v ----
    #pragma unroll
    for (int q = 0; q < 4; q++) {
        int idx = tid + q * 256;
        int il = idx >> 6, m = idx & 63;
        int mr = (64 - m) & 63;
        float a = hps[il][m], bb = hps[il][mr];
        us[il][m] = a + bb;
        vs[il][m] = a - bb;
    }
    __syncthreads();

    // ---- phase 4: hz[o][m] = 0.5*sum_i( u[i][m]*hq[m][i*16+o] + v[i][m]*hq[mr][i*16+o] )
    #pragma unroll
    for (int q = 0; q < 4; q++) {
        int idx = tid + q * 256;
        int m = idx >> 4, o = idx & 15;
        int mr = (64 - m) & 63;
        const float* hq1 = g_hq + m  * 256 + o;
        const float* hq2 = g_hq + mr * 256 + o;
        float acc = 0.f;
        #pragma unroll
        for (int i = 0; i < 16; i++) {
            acc = fmaf(us[i][m], hq1[i * 16], acc);
            acc = fmaf(vs[i][m], hq2[i * 16], acc);
        }
        hzs[o][m] = 0.5f * acc;
    }
    __syncthreads();

    // ---- phase 5: z[o][m'] = (sum_m hz[o][m] * cs[m][m']) / 4096, store transposed
    #pragma unroll
    for (int q = 0; q < 4; q++) {
        int idx = tid + q * 256;
        int o = idx >> 6, mp = idx & 63;
        float acc = 0.f;
        #pragma unroll
        for (int m = 0; m < 64; m++)
            acc = fmaf(hzs[o][m], cs[m][mp], acc);
        g_zT[mp * 64 + b * 16 + o] = acc * (1.0f / 4096.0f);
    }
}

// ============================================================
// K3: out[r][k] = (sum_m z[r][m] * cas(2*pi*m*k/4097)) / 262208
// ============================================================
__global__ void k_out(float* __restrict__ out)
{
    __shared__ float zs[64][68];   // [m][r] padded
    __shared__ float Cs[64][36];   // [m][kt] padded

    const int blk = blockIdx.x;          // 129 blocks, 32 k each
    const int tid = threadIdx.x;         // 256
    const int kbase = blk * 32;

    for (int idx = tid; idx < 4096; idx += 256)
        zs[idx >> 6][idx & 63] = g_zT[idx];

    const float W2 = 2.0f * CUDART_PI_F / 4097.0f;
    for (int idx = tid; idx < 2048; idx += 256) {
        int mm = idx >> 5, kt = idx & 31;
        int k = kbase + kt;
        float val = 0.f;
        if (k < N2) {
            int t = (mm * k) % 4097;
            float s, c;
            __sincosf((float)t * W2, &s, &c);
            val = c + s;
        }
        Cs[mm][kt] = val;
    }
    __syncthreads();

    const int ktq = tid & 15, rq = tid >> 4;
    const int r0 = rq * 4, k0 = ktq * 2;
    float acc[4][2] = {};
    #pragma unroll
    for (int mm = 0; mm < 64; mm++) {
        float4 zv = *reinterpret_cast<const float4*>(&zs[mm][r0]);
        float2 cv = *reinterpret_cast<const float2*>(&Cs[mm][k0]);
        acc[0][0] = fmaf(zv.x, cv.x, acc[0][0]);
        acc[0][1] = fmaf(zv.x, cv.y, acc[0][1]);
        acc[1][0] = fmaf(zv.y, cv.x, acc[1][0]);
        acc[1][1] = fmaf(zv.y, cv.y, acc[1][1]);
        acc[2][0] = fmaf(zv.z, cv.x, acc[2][0]);
        acc[2][1] = fmaf(zv.z, cv.y, acc[2][1]);
        acc[3][0] = fmaf(zv.w, cv.x, acc[3][0]);
        acc[3][1] = fmaf(zv.w, cv.y, acc[3][1]);
    }
    const float SCL = 1.0f / 262208.0f;
    #pragma unroll
    for (int ri = 0; ri < 4; ri++) {
        #pragma unroll
        for (int ki = 0; ki < 2; ki++) {
            int k = kbase + k0 + ki;
            if (k < N2)
                out[(r0 + ri) * N2 + k] = acc[ri][ki] * SCL;
        }
    }
}

// ============================================================
extern "C" void kernel_launch(void* const* d_in, const int* in_sizes, int n_in,
                              void* d_out, int out_size)
{
    const float* x = (const float*)d_in[0];   // [4,16,8192]
    const float* w = (const float*)d_in[1];   // [16,16,64]
    float* out = (float*)d_out;               // [4,16,4097]

    k_stage1<<<144, 256>>>(x, w);
    k_mid<<<4, 256>>>();
    k_out<<<129, 256>>>(out);
}

// round 3
// speedup vs baseline: 1.3367x; 1.0689x over previous
#include <cuda_runtime.h>
#include <math_constants.h>

// x: [4,16,8192] f32 ; weights1: [16,16,64] f32 ; out: [4,16,4097] f32
#define RWS   64
#define NN    8192
#define MM    64
#define N2    4097
#define NPART 128

// -------- device scratch --------
__device__ float g_P[NPART * RWS * MM];   // stage-1 partials (2 MB)
__device__ float g_hq[MM * 256];          // hq transposed: [m][u], u = i*16+o
__device__ float g_zT[MM * RWS];          // z transposed: [m'][r]

// ============================================================
// K1: blocks [0,128): partial Y = X @ cas8192[:, :64]  (split over n)
//     blocks [128,144): hq = W @ cas64  (transposed store)
// ============================================================
__global__ void k_stage1(const float* __restrict__ x, const float* __restrict__ w)
{
    __shared__ float Xs[64][68];   // [n_local][r]
    __shared__ float Cs[64][68];   // [n_local][k] / [j][m]
    __shared__ float ws[16][64];
    __shared__ float v64[64];

    const int blk = blockIdx.x;
    const int tid = threadIdx.x;

    if (blk < NPART) {
        const int n0 = blk * 64;
        for (int idx = tid; idx < 64 * 16; idx += 256) {
            int row = idx >> 4;
            int c4  = (idx & 15) * 4;
            float4 v = *reinterpret_cast<const float4*>(x + row * NN + n0 + c4);
            Xs[c4 + 0][row] = v.x;
            Xs[c4 + 1][row] = v.y;
            Xs[c4 + 2][row] = v.z;
            Xs[c4 + 3][row] = v.w;
        }
        // cas table via rotation recurrence: 2 sincos/thread instead of 16
        {
            const float W0 = 2.0f * CUDART_PI_F / 8192.0f;
            const int nl = tid >> 2;
            const int k0 = (tid & 3) * 16;
            unsigned nm = (unsigned)(n0 + nl) & 8191u;
            unsigned t0 = (nm * (unsigned)k0) & 8191u;
            float s0, c0, sd, cd;
            __sincosf((float)t0 * W0, &s0, &c0);
            __sincosf((float)nm * W0, &sd, &cd);
            float c = c0, s = s0;
            #pragma unroll
            for (int j = 0; j < 16; j++) {
                Cs[nl][k0 + j] = c + s;
                float cn = fmaf(c, cd, -s * sd);
                float sn = fmaf(s, cd,  c * sd);
                c = cn; s = sn;
            }
        }
        __syncthreads();

        const int kq = tid & 15, rq = tid >> 4;
        const int r0 = rq * 4, k0 = kq * 4;
        float acc[4][4] = {};
        #pragma unroll
        for (int nl = 0; nl < 64; nl++) {
            float4 xv = *reinterpret_cast<const float4*>(&Xs[nl][r0]);
            float4 cv = *reinterpret_cast<const float4*>(&Cs[nl][k0]);
            float xr[4] = {xv.x, xv.y, xv.z, xv.w};
            float ck[4] = {cv.x, cv.y, cv.z, cv.w};
            #pragma unroll
            for (int a = 0; a < 4; a++)
                #pragma unroll
                for (int b = 0; b < 4; b++)
                    acc[a][b] = fmaf(xr[a], ck[b], acc[a][b]);
        }
        float* P = g_P + blk * (RWS * MM);
        #pragma unroll
        for (int a = 0; a < 4; a++) {
            float4 v = make_float4(acc[a][0], acc[a][1], acc[a][2], acc[a][3]);
            *reinterpret_cast<float4*>(P + (r0 + a) * 64 + k0) = v;
        }
    } else {
        // hq block: cas64 has only 64 distinct values -> smem gather
        const int u0 = (blk - 128) * 16;
        for (int idx = tid; idx < 1024; idx += 256)
            ws[idx >> 6][idx & 63] = w[u0 * 64 + idx];
        if (tid < 64) {
            const float W1 = 2.0f * CUDART_PI_F / 64.0f;
            float s, c;
            __sincosf((float)tid * W1, &s, &c);
            v64[tid] = c + s;
        }
        __syncthreads();
        for (int idx = tid; idx < 4096; idx += 256) {
            int j = idx >> 6, m = idx & 63;
            Cs[j][m] = v64[(j * m) & 63];
        }
        __syncthreads();

        const int ul = tid >> 4, mq = tid & 15, m0 = mq * 4;
        float acc[4] = {};
        #pragma unroll
        for (int j = 0; j < 64; j++) {
            float wv = ws[ul][j];
            float4 cv = *reinterpret_cast<const float4*>(&Cs[j][m0]);
            acc[0] = fmaf(wv, cv.x, acc[0]);
            acc[1] = fmaf(wv, cv.y, acc[1]);
            acc[2] = fmaf(wv, cv.z, acc[2]);
            acc[3] = fmaf(wv, cv.w, acc[3]);
        }
        #pragma unroll
        for (int e = 0; e < 4; e++)
            g_hq[(m0 + e) * 256 + u0 + ul] = acc[e];
    }
}

// ============================================================
// K2: fused reduce + hp + (u,v) + hz + z.  One block per batch b.
// ============================================================
__global__ void k_mid()
{
    __shared__ float Ys [16][68];
    __shared__ float cs [64][68];
    __shared__ float hps[16][68];
    __shared__ float us [16][68];
    __shared__ float vs [16][68];
    __shared__ float hzs[16][68];
    __shared__ float v64[64];

    const int b   = blockIdx.x;
    const int tid = threadIdx.x;   // 256

    // cas64 base values (64 sincos total)
    if (tid < 64) {
        const float W1 = 2.0f * CUDART_PI_F / 64.0f;
        float s, c;
        __sincosf((float)tid * W1, &s, &c);
        v64[tid] = c + s;
    }

    // split-K reduce for this block's 16 Y rows (overlaps with v64)
    {
        const float* P = g_P + b * 1024 + tid * 4;
        float4 a0 = {0,0,0,0}, a1 = {0,0,0,0}, a2 = {0,0,0,0}, a3 = {0,0,0,0};
        #pragma unroll 4
        for (int p = 0; p < NPART; p += 4) {
            float4 v0 = *reinterpret_cast<const float4*>(P + (p + 0) * 4096);
            float4 v1 = *reinterpret_cast<const float4*>(P + (p + 1) * 4096);
            float4 v2 = *reinterpret_cast<const float4*>(P + (p + 2) * 4096);
            float4 v3 = *reinterpret_cast<const float4*>(P + (p + 3) * 4096);
            a0.x += v0.x; a0.y += v0.y; a0.z += v0.z; a0.w += v0.w;
            a1.x += v1.x; a1.y += v1.y; a1.z += v1.z; a1.w += v1.w;
            a2.x += v2.x; a2.y += v2.y; a2.z += v2.z; a2.w += v2.w;
            a3.x += v3.x; a3.y += v3.y; a3.z += v3.z; a3.w += v3.w;
        }
        float4 a;
        a.x = (a0.x + a1.x) + (a2.x + a3.x);
        a.y = (a0.y + a1.y) + (a2.y + a3.y);
        a.z = (a0.z + a1.z) + (a2.z + a3.z);
        a.w = (a0.w + a1.w) + (a2.w + a3.w);
        int il = tid >> 4, k0 = (tid & 15) * 4;
        *reinterpret_cast<float4*>(&Ys[il][k0]) = a;
    }
    __syncthreads();

    // materialize cs from v64 gather
    for (int idx = tid; idx < 4096; idx += 256) {
        int j = idx >> 6, m = idx & 63;
        cs[j][m] = v64[(j * m) & 63];
    }
    __syncthreads();

    // hp[il][m] = sum_k Ys[il][k] * cs[k][m]
    #pragma unroll
    for (int q = 0; q < 4; q++) {
        int idx = tid + q * 256;
        int il = idx >> 6, m = idx & 63;
        float acc = 0.f;
        #pragma unroll
        for (int k = 0; k < 64; k++)
            acc = fmaf(Ys[il][k], cs[k][m], acc);
        hps[il][m] = acc;
    }
    __syncthreads();

    // u,v
    #pragma unroll
    for (int q = 0; q < 4; q++) {
        int idx = tid + q * 256;
        int il = idx >> 6, m = idx & 63;
        int mr = (64 - m) & 63;
        float a = hps[il][m], bb = hps[il][mr];
        us[il][m] = a + bb;
        vs[il][m] = a - bb;
    }
    __syncthreads();

    // hz[o][m] = 0.5*sum_i( u[i][m]*hq[m][i*16+o] + v[i][m]*hq[mr][i*16+o] )
    #pragma unroll
    for (int q = 0; q < 4; q++) {
        int idx = tid + q * 256;
        int m = idx >> 4, o = idx & 15;
        int mr = (64 - m) & 63;
        const float* hq1 = g_hq + m  * 256 + o;
        const float* hq2 = g_hq + mr * 256 + o;
        float acc = 0.f;
        #pragma unroll
        for (int i = 0; i < 16; i++) {
            acc = fmaf(us[i][m], hq1[i * 16], acc);
            acc = fmaf(vs[i][m], hq2[i * 16], acc);
        }
        hzs[o][m] = 0.5f * acc;
    }
    __syncthreads();

    // z[o][m'] = (sum_m hz[o][m] * cs[m][m']) / 4096, stored transposed
    #pragma unroll
    for (int q = 0; q < 4; q++) {
        int idx = tid + q * 256;
        int o = idx >> 6, mp = idx & 63;
        float acc = 0.f;
        #pragma unroll
        for (int m = 0; m < 64; m++)
            acc = fmaf(hzs[o][m], cs[m][mp], acc);
        g_zT[mp * 64 + b * 16 + o] = acc * (1.0f / 4096.0f);
    }
}

// ============================================================
// K3: out[r][k] = (sum_m z[r][m] * cas(2*pi*m*k/4097)) / 262208
// ============================================================
__global__ void k_out(float* __restrict__ out)
{
    __shared__ float zs[64][68];   // [m][r]
    __shared__ float Cs[64][36];   // [m][kt]

    const int blk = blockIdx.x;          // 129 blocks, 32 k each
    const int tid = threadIdx.x;         // 256
    const int kbase = blk * 32;

    for (int idx = tid; idx < 4096; idx += 256)
        zs[idx >> 6][idx & 63] = g_zT[idx];

    // cas table via rotation recurrence: 2 sincos/thread instead of 8
    {
        const float W2 = 2.0f * CUDART_PI_F / 4097.0f;
        const int mm = tid >> 2;
        const int kt0 = (tid & 3) * 8;
        int k0 = kbase + kt0;
        int t0 = (mm * k0) % 4097;
        float s0, c0, sd, cd;
        __sincosf((float)t0 * W2, &s0, &c0);
        __sincosf((float)mm * W2, &sd, &cd);
        float c = c0, s = s0;
        #pragma unroll
        for (int j = 0; j < 8; j++) {
            Cs[mm][kt0 + j] = c + s;
            float cn = fmaf(c, cd, -s * sd);
            float sn = fmaf(s, cd,  c * sd);
            c = cn; s = sn;
        }
    }
    __syncthreads();

    const int ktq = tid & 15, rq = tid >> 4;
    const int r0 = rq * 4, k0 = ktq * 2;
    float acc[4][2] = {};
    #pragma unroll
    for (int mm = 0; mm < 64; mm++) {
        float4 zv = *reinterpret_cast<const float4*>(&zs[mm][r0]);
        float2 cv = *reinterpret_cast<const float2*>(&Cs[mm][k0]);
        acc[0][0] = fmaf(zv.x, cv.x, acc[0][0]);
        acc[0][1] = fmaf(zv.x, cv.y, acc[0][1]);
        acc[1][0] = fmaf(zv.y, cv.x, acc[1][0]);
        acc[1][1] = fmaf(zv.y, cv.y, acc[1][1]);
        acc[2][0] = fmaf(zv.z, cv.x, acc[2][0]);
        acc[2][1] = fmaf(zv.z, cv.y, acc[2][1]);
        acc[3][0] = fmaf(zv.w, cv.x, acc[3][0]);
        acc[3][1] = fmaf(zv.w, cv.y, acc[3][1]);
    }
    const float SCL = 1.0f / 262208.0f;
    #pragma unroll
    for (int ri = 0; ri < 4; ri++) {
        #pragma unroll
        for (int ki = 0; ki < 2; ki++) {
            int k = kbase + k0 + ki;
            if (k < N2)
                out[(r0 + ri) * N2 + k] = acc[ri][ki] * SCL;
        }
    }
}

// ============================================================
extern "C" void kernel_launch(void* const* d_in, const int* in_sizes, int n_in,
                              void* d_out, int out_size)
{
    const float* x = (const float*)d_in[0];   // [4,16,8192]
    const float* w = (const float*)d_in[1];   // [16,16,64]
    float* out = (float*)d_out;               // [4,16,4097]

    k_stage1<<<144, 256>>>(x, w);
    k_mid<<<4, 256>>>();
    k_out<<<129, 256>>>(out);
}

// round 4
// speedup vs baseline: 1.6000x; 1.1969x over previous
#include <cuda_runtime.h>
#include <math_constants.h>

// x: [4,16,8192] f32 ; weights1: [16,16,64] f32 ; out: [4,16,4097] f32
#define NN    8192
#define MM    64
#define N2    4097
#define NPART 128
#define NBLK  148
#define NTHR  512

// -------- device scratch --------
__device__ float g_P[NPART * 64 * 64];    // stage-1 partials (2 MB) [p][r*64+k]
__device__ float g_hq[MM * 256];          // hq transposed: [m][u], u = i*16+o
__device__ float g_zT[MM * 64];           // z transposed: [m'][r]

// -------- grid barrier (all 148 blocks resident by construction) --------
__device__ unsigned g_bar_count = 0;
__device__ unsigned g_bar_gen   = 0;

__device__ __forceinline__ void grid_bar()
{
    __syncthreads();
    if (threadIdx.x == 0) {
        __threadfence();
        unsigned gen = *(volatile unsigned*)&g_bar_gen;
        unsigned arrived = atomicAdd(&g_bar_count, 1u) + 1u;
        if (arrived == (unsigned)NBLK) {
            g_bar_count = 0;
            __threadfence();
            *(volatile unsigned*)&g_bar_gen = gen + 1u;
        } else {
            while (*(volatile unsigned*)&g_bar_gen == gen) __nanosleep(64);
        }
        __threadfence();
    }
    __syncthreads();
}

// -------- shared memory union --------
struct SmemA {
    float Xs[64][68];   // [n_local][r]  (reused as combine scratch after GEMM)
    float Cs[64][68];   // [n_local][k] / [j][m]
    float ws[16][64];
    float v64[64];
};
struct SmemB {
    float Ys [16][68];
    float cs [64][68];
    float hps[16][68];  // start also aliased as reduce scratch (8KB spans hps+us)
    float us [16][68];
    float vs [16][68];
    float hzs[16][68];
    float v64[64];
};
struct SmemC {
    float zs[64][68];   // [m'][r]
    float Cs[64][36];   // [m'][kt]
};
union SmemU { SmemA a; SmemB b; SmemC c; };

__global__ __launch_bounds__(NTHR, 1)
void k_fused(const float* __restrict__ x, const float* __restrict__ w,
             float* __restrict__ out)
{
    __shared__ SmemU sm;
    const int blk = blockIdx.x;
    const int tid = threadIdx.x;

    // ================= PHASE A =================
    if (blk < NPART) {
        // partial Y = X @ cas8192[:, :64] over n-chunk [n0, n0+64)
        const int n0 = blk * 64;
        // load X chunk transposed: Xs[nl][r]
        #pragma unroll
        for (int q = 0; q < 2; q++) {
            int idx = tid + q * NTHR;            // 0..1023
            int row = idx >> 4;
            int c4  = (idx & 15) * 4;
            float4 v = *reinterpret_cast<const float4*>(x + row * NN + n0 + c4);
            sm.a.Xs[c4 + 0][row] = v.x;
            sm.a.Xs[c4 + 1][row] = v.y;
            sm.a.Xs[c4 + 2][row] = v.z;
            sm.a.Xs[c4 + 3][row] = v.w;
        }
        // cas table via rotation recurrence (8 entries/thread)
        {
            const float W0 = 2.0f * CUDART_PI_F / 8192.0f;
            const int nl = tid >> 3;
            const int k0 = (tid & 7) * 8;
            unsigned nm = (unsigned)(n0 + nl) & 8191u;
            unsigned t0 = (nm * (unsigned)k0) & 8191u;
            float s0, c0, sd, cd;
            __sincosf((float)t0 * W0, &s0, &c0);
            __sincosf((float)nm * W0, &sd, &cd);
            float c = c0, s = s0;
            #pragma unroll
            for (int j = 0; j < 8; j++) {
                sm.a.Cs[nl][k0 + j] = c + s;
                float cn = fmaf(c, cd, -s * sd);
                float sn = fmaf(s, cd,  c * sd);
                c = cn; s = sn;
            }
        }
        __syncthreads();

        // split-n within block: half h covers nl in [32h, 32h+32)
        const int half = tid >> 8;
        const int tid2 = tid & 255;
        const int kq = tid2 & 15, rq = tid2 >> 4;
        const int r0 = rq * 4, k0 = kq * 4;
        const int nb = half * 32;
        float acc[4][4] = {};
        #pragma unroll
        for (int j = 0; j < 32; j++) {
            int nl = nb + j;
            float4 xv = *reinterpret_cast<const float4*>(&sm.a.Xs[nl][r0]);
            float4 cv = *reinterpret_cast<const float4*>(&sm.a.Cs[nl][k0]);
            float xr[4] = {xv.x, xv.y, xv.z, xv.w};
            float ck[4] = {cv.x, cv.y, cv.z, cv.w};
            #pragma unroll
            for (int a = 0; a < 4; a++)
                #pragma unroll
                for (int b = 0; b < 4; b++)
                    acc[a][b] = fmaf(xr[a], ck[b], acc[a][b]);
        }
        __syncthreads();
        // combine halves via smem scratch (reuse Xs area), interleaved layout
        float4* scratch = reinterpret_cast<float4*>(&sm.a.Xs[0][0]); // [4][256]
        if (half == 1) {
            #pragma unroll
            for (int a = 0; a < 4; a++)
                scratch[a * 256 + tid2] =
                    make_float4(acc[a][0], acc[a][1], acc[a][2], acc[a][3]);
        }
        __syncthreads();
        if (half == 0) {
            float* P = g_P + blk * 4096;
            #pragma unroll
            for (int a = 0; a < 4; a++) {
                float4 o = scratch[a * 256 + tid2];
                o.x += acc[a][0]; o.y += acc[a][1];
                o.z += acc[a][2]; o.w += acc[a][3];
                *reinterpret_cast<float4*>(P + (r0 + a) * 64 + k0) = o;
            }
        }
    } else if (blk < NPART + 16) {
        // hq block: hq[u][m] = sum_j w[u][j]*cas64[j][m], store transposed
        const int u0 = (blk - NPART) * 16;
        #pragma unroll
        for (int q = 0; q < 2; q++) {
            int idx = tid + q * NTHR;
            sm.a.ws[idx >> 6][idx & 63] = w[u0 * 64 + idx];
        }
        if (tid < 64) {
            const float W1 = 2.0f * CUDART_PI_F / 64.0f;
            float s, c;
            __sincosf((float)tid * W1, &s, &c);
            sm.a.v64[tid] = c + s;
        }
        __syncthreads();
        #pragma unroll
        for (int q = 0; q < 8; q++) {
            int idx = tid + q * NTHR;  // 0..4095
            int j = idx >> 6, m = idx & 63;
            sm.a.Cs[j][m] = sm.a.v64[(j * m) & 63];
        }
        __syncthreads();
        #pragma unroll
        for (int q = 0; q < 2; q++) {
            int idx = tid + q * NTHR;  // 0..1023
            int ul = idx >> 6, m = idx & 63;
            float acc = 0.f;
            #pragma unroll
            for (int j = 0; j < 64; j++)
                acc = fmaf(sm.a.ws[ul][j], sm.a.Cs[j][m], acc);
            g_hq[m * 256 + u0 + ul] = acc;
        }
    }

    grid_bar();

    // ================= PHASE B (blocks 0-3) =================
    if (blk < 4) {
        const int b = blk;
        if (tid < 64) {
            const float W1 = 2.0f * CUDART_PI_F / 64.0f;
            float s, c;
            __sincosf((float)tid * W1, &s, &c);
            sm.b.v64[tid] = c + s;
        }
        // split-K reduce: thread = (p-half, float4 pos)
        {
            const int pos  = tid & 255;
            const int half = tid >> 8;
            const float* P = g_P + half * 64 * 4096 + b * 1024 + pos * 4;
            float4 a0 = {0,0,0,0}, a1 = {0,0,0,0}, a2 = {0,0,0,0}, a3 = {0,0,0,0};
            #pragma unroll 4
            for (int p = 0; p < 64; p += 4) {
                float4 v0 = *reinterpret_cast<const float4*>(P + (p + 0) * 4096);
                float4 v1 = *reinterpret_cast<const float4*>(P + (p + 1) * 4096);
                float4 v2 = *reinterpret_cast<const float4*>(P + (p + 2) * 4096);
                float4 v3 = *reinterpret_cast<const float4*>(P + (p + 3) * 4096);
                a0.x += v0.x; a0.y += v0.y; a0.z += v0.z; a0.w += v0.w;
                a1.x += v1.x; a1.y += v1.y; a1.z += v1.z; a1.w += v1.w;
                a2.x += v2.x; a2.y += v2.y; a2.z += v2.z; a2.w += v2.w;
                a3.x += v3.x; a3.y += v3.y; a3.z += v3.z; a3.w += v3.w;
            }
            float4 a;
            a.x = (a0.x + a1.x) + (a2.x + a3.x);
            a.y = (a0.y + a1.y) + (a2.y + a3.y);
            a.z = (a0.z + a1.z) + (a2.z + a3.z);
            a.w = (a0.w + a1.w) + (a2.w + a3.w);
            float4* Ys2 = reinterpret_cast<float4*>(&sm.b.hps[0][0]); // [2][256]
            Ys2[half * 256 + pos] = a;
        }
        __syncthreads();
        if (tid < 256) {
            float4* Ys2 = reinterpret_cast<float4*>(&sm.b.hps[0][0]);
            float4 u = Ys2[tid], v = Ys2[256 + tid];
            float4 a = make_float4(u.x + v.x, u.y + v.y, u.z + v.z, u.w + v.w);
            int il = tid >> 4, k0 = (tid & 15) * 4;
            *reinterpret_cast<float4*>(&sm.b.Ys[il][k0]) = a;
        }
        __syncthreads();
        // materialize cs from v64
        #pragma unroll
        for (int q = 0; q < 8; q++) {
            int idx = tid + q * NTHR;
            int j = idx >> 6, m = idx & 63;
            sm.b.cs[j][m] = sm.b.v64[(j * m) & 63];
        }
        __syncthreads();
        // hp
        #pragma unroll
        for (int q = 0; q < 2; q++) {
            int idx = tid + q * NTHR;  // 0..1023
            int il = idx >> 6, m = idx & 63;
            float acc = 0.f;
            #pragma unroll
            for (int k = 0; k < 64; k++)
                acc = fmaf(sm.b.Ys[il][k], sm.b.cs[k][m], acc);
            sm.b.hps[il][m] = acc;
        }
        __syncthreads();
        // u, v
        #pragma unroll
        for (int q = 0; q < 2; q++) {
            int idx = tid + q * NTHR;
            int il = idx >> 6, m = idx & 63;
            int mr = (64 - m) & 63;
            float a = sm.b.hps[il][m], bb = sm.b.hps[il][mr];
            sm.b.us[il][m] = a + bb;
            sm.b.vs[il][m] = a - bb;
        }
        __syncthreads();
        // hz
        #pragma unroll
        for (int q = 0; q < 2; q++) {
            int idx = tid + q * NTHR;
            int m = idx >> 4, o = idx & 15;
            int mr = (64 - m) & 63;
            const float* hq1 = g_hq + m  * 256 + o;
            const float* hq2 = g_hq + mr * 256 + o;
            float acc = 0.f;
            #pragma unroll
            for (int i = 0; i < 16; i++) {
                acc = fmaf(sm.b.us[i][m], hq1[i * 16], acc);
                acc = fmaf(sm.b.vs[i][m], hq2[i * 16], acc);
            }
            sm.b.hzs[o][m] = 0.5f * acc;
        }
        __syncthreads();
        // z transposed
        #pragma unroll
        for (int q = 0; q < 2; q++) {
            int idx = tid + q * NTHR;
            int o = idx >> 6, mp = idx & 63;
            float acc = 0.f;
            #pragma unroll
            for (int m = 0; m < 64; m++)
                acc = fmaf(sm.b.hzs[o][m], sm.b.cs[m][mp], acc);
            g_zT[mp * 64 + b * 16 + o] = acc * (1.0f / 4096.0f);
        }
    }

    grid_bar();

    // ================= PHASE C (blocks 0-128) =================
    if (blk < 129) {
        const int kbase = blk * 32;
        // load zT (16KB, hot in L2)
        #pragma unroll
        for (int q = 0; q < 2; q++) {
            int i4 = tid + q * NTHR;   // 0..1023 float4 positions
            float4 v = *reinterpret_cast<const float4*>(g_zT + i4 * 4);
            int f = i4 * 4;
            *reinterpret_cast<float4*>(&sm.c.zs[f >> 6][f & 63]) = v;
        }
        // cas table via rotation recurrence (4 entries/thread over 64x32)
        {
            const float W2 = 2.0f * CUDART_PI_F / 4097.0f;
            const int mm = tid >> 3;
            const int kt0 = (tid & 7) * 4;
            int k0 = kbase + kt0;
            int t0 = (mm * k0) % 4097;
            float s0, c0, sd, cd;
            __sincosf((float)t0 * W2, &s0, &c0);
            __sincosf((float)mm * W2, &sd, &cd);
            float c = c0, s = s0;
            #pragma unroll
            for (int j = 0; j < 4; j++) {
                sm.c.Cs[mm][kt0 + j] = c + s;
                float cn = fmaf(c, cd, -s * sd);
                float sn = fmaf(s, cd,  c * sd);
                c = cn; s = sn;
            }
        }
        __syncthreads();

        // 4 rows x 1 k per thread; zs read is warp-broadcast
        const int ktq = tid & 31;          // k within chunk (same warp spans all k)
        const int rq  = tid >> 5;          // 0..15
        const int r0  = rq * 4;
        const int k   = kbase + ktq;
        float a0 = 0.f, a1 = 0.f, a2 = 0.f, a3 = 0.f;
        #pragma unroll
        for (int mm = 0; mm < 64; mm++) {
            float4 zv = *reinterpret_cast<const float4*>(&sm.c.zs[mm][r0]);
            float cv = sm.c.Cs[mm][ktq];
            a0 = fmaf(zv.x, cv, a0);
            a1 = fmaf(zv.y, cv, a1);
            a2 = fmaf(zv.z, cv, a2);
            a3 = fmaf(zv.w, cv, a3);
        }
        const float SCL = 1.0f / 262208.0f;
        if (k < N2) {
            out[(r0 + 0) * N2 + k] = a0 * SCL;
            out[(r0 + 1) * N2 + k] = a1 * SCL;
            out[(r0 + 2) * N2 + k] = a2 * SCL;
            out[(r0 + 3) * N2 + k] = a3 * SCL;
        }
    }
}

// ============================================================
extern "C" void kernel_launch(void* const* d_in, const int* in_sizes, int n_in,
                              void* d_out, int out_size)
{
    const float* x = (const float*)d_in[0];   // [4,16,8192]
    const float* w = (const float*)d_in[1];   // [16,16,64]
    float* out = (float*)d_out;               // [4,16,4097]

    k_fused<<<NBLK, NTHR>>>(x, w, out);
}